// round 15
// baseline (speedup 1.0000x reference)
#include <cuda_runtime.h>
#include <math.h>

// Problem dims
#define LC 512   // sequence length
#define NB 64    // batch
#define HD 512   // hidden = input size
#define CSZ 8    // cluster size (CTAs per cluster)
#define RG 128   // scan CTAs total: 16 clusters x 8 CTAs
#define RT 512   // threads per scan CTA
#define RPC 4    // batch rows per cluster
#define COLS_PER_CTA 64

// ---------------- f32x2 packed-FMA helpers (sm_103a FFMA2) ----------------
union U64F2 {
    unsigned long long u;
    float2 f;
};

__device__ __forceinline__ void ffma2(unsigned long long& d,
                                      unsigned long long a,
                                      unsigned long long b) {
    asm("fma.rn.f32x2 %0, %1, %2, %0;" : "+l"(d) : "l"(a), "l"(b));
}

__device__ __forceinline__ unsigned long long dupf(float a) {
    unsigned long long d;
    unsigned int ai = __float_as_uint(a);
    asm("mov.b64 %0, {%1, %1};" : "=l"(d) : "r"(ai));
    return d;
}

// ---------------- cluster helpers ----------------------------------------
__device__ __forceinline__ unsigned int ctarank() {
    unsigned int r;
    asm("mov.u32 %0, %%cluster_ctarank;" : "=r"(r));
    return r;
}

__device__ __forceinline__ unsigned int smem_u32(const void* p) {
    unsigned int a;
    asm("{ .reg .u64 t; cvta.to.shared.u64 t, %1; cvt.u32.u64 %0, t; }"
        : "=r"(a) : "l"(p));
    return a;
}

__device__ __forceinline__ void st_cluster_f32(unsigned int saddr,
                                               unsigned int rank, float v) {
    unsigned int ra;
    asm volatile("mapa.shared::cluster.u32 %0, %1, %2;"
                 : "=r"(ra) : "r"(saddr), "r"(rank));
    asm volatile("st.shared::cluster.f32 [%0], %1;" :: "r"(ra), "f"(v)
                 : "memory");
}

__device__ __forceinline__ void cluster_sync() {
    asm volatile("barrier.cluster.arrive.aligned;" ::: "memory");
    asm volatile("barrier.cluster.wait.aligned;" ::: "memory");
}

// ---------------- device scratch (module-load allocations, legal) ---------
__device__ float g_A0[LC * NB * HD];   // x @ Wih0^T + bih0 + bhh0
__device__ float g_H0[LC * NB * HD];   // all layer-0 hidden states
__device__ float g_X1[LC * NB * HD];   // H0 @ Wih1^T + bih1 + bhh1

// ---------------- GEMM v2 (validated R14): 128x128 tile, 8x8 micro --------
// A[m][j] = sum_i X[m][i]*W[j][i] + bih[j] + bhh[j]
#define GK 16
__global__ __launch_bounds__(256) void gemm_xW_kernel(
    const float* __restrict__ X, const float* __restrict__ W,
    const float* __restrict__ bih, const float* __restrict__ bhh,
    float* __restrict__ A0)
{
    __shared__ __align__(16) float As[2][GK][132];  // As[buf][k][m]
    __shared__ __align__(16) float Ws[2][GK][132];  // Ws[buf][k][j]

    const int m0 = blockIdx.y * 128;
    const int j0 = blockIdx.x * 128;
    const int tid = threadIdx.x;
    const int tx = tid & 15;
    const int ty = tid >> 4;

    const int r  = tid >> 1;
    const int c0 = (tid & 1) * 2;

    unsigned long long acc[8][4];
#pragma unroll
    for (int i = 0; i < 8; i++)
#pragma unroll
        for (int jp = 0; jp < 4; jp++) acc[i][jp] = 0ULL;

    {
        float4 xv0 = __ldg((const float4*)&X[(m0 + r) * HD + (c0 + 0) * 4]);
        float4 xv1 = __ldg((const float4*)&X[(m0 + r) * HD + (c0 + 1) * 4]);
        float4 wv0 = __ldg((const float4*)&W[(j0 + r) * HD + (c0 + 0) * 4]);
        float4 wv1 = __ldg((const float4*)&W[(j0 + r) * HD + (c0 + 1) * 4]);
        As[0][c0 * 4 + 0][r] = xv0.x; As[0][c0 * 4 + 1][r] = xv0.y;
        As[0][c0 * 4 + 2][r] = xv0.z; As[0][c0 * 4 + 3][r] = xv0.w;
        As[0][c0 * 4 + 4][r] = xv1.x; As[0][c0 * 4 + 5][r] = xv1.y;
        As[0][c0 * 4 + 6][r] = xv1.z; As[0][c0 * 4 + 7][r] = xv1.w;
        Ws[0][c0 * 4 + 0][r] = wv0.x; Ws[0][c0 * 4 + 1][r] = wv0.y;
        Ws[0][c0 * 4 + 2][r] = wv0.z; Ws[0][c0 * 4 + 3][r] = wv0.w;
        Ws[0][c0 * 4 + 4][r] = wv1.x; Ws[0][c0 * 4 + 5][r] = wv1.y;
        Ws[0][c0 * 4 + 6][r] = wv1.z; Ws[0][c0 * 4 + 7][r] = wv1.w;
    }
    __syncthreads();

    for (int kc = 0; kc < HD / GK; kc++) {
        const int buf = kc & 1;
        float4 xv0, xv1, wv0, wv1;
        const bool more = (kc + 1 < HD / GK);
        if (more) {
            const int k0 = (kc + 1) * GK;
            xv0 = __ldg((const float4*)&X[(m0 + r) * HD + k0 + (c0 + 0) * 4]);
            xv1 = __ldg((const float4*)&X[(m0 + r) * HD + k0 + (c0 + 1) * 4]);
            wv0 = __ldg((const float4*)&W[(j0 + r) * HD + k0 + (c0 + 0) * 4]);
            wv1 = __ldg((const float4*)&W[(j0 + r) * HD + k0 + (c0 + 1) * 4]);
        }

#pragma unroll
        for (int k = 0; k < GK; k++) {
            float4 alo = *(const float4*)&As[buf][k][ty * 4];
            float4 ahi = *(const float4*)&As[buf][k][64 + ty * 4];
            ulonglong2 blo = *(const ulonglong2*)&Ws[buf][k][tx * 4];
            ulonglong2 bhi = *(const ulonglong2*)&Ws[buf][k][64 + tx * 4];
            unsigned long long am[8] = {
                dupf(alo.x), dupf(alo.y), dupf(alo.z), dupf(alo.w),
                dupf(ahi.x), dupf(ahi.y), dupf(ahi.z), dupf(ahi.w)};
#pragma unroll
            for (int i = 0; i < 8; i++) {
                ffma2(acc[i][0], am[i], blo.x);
                ffma2(acc[i][1], am[i], blo.y);
                ffma2(acc[i][2], am[i], bhi.x);
                ffma2(acc[i][3], am[i], bhi.y);
            }
        }

        if (more) {
            const int nb = buf ^ 1;
            As[nb][c0 * 4 + 0][r] = xv0.x; As[nb][c0 * 4 + 1][r] = xv0.y;
            As[nb][c0 * 4 + 2][r] = xv0.z; As[nb][c0 * 4 + 3][r] = xv0.w;
            As[nb][c0 * 4 + 4][r] = xv1.x; As[nb][c0 * 4 + 5][r] = xv1.y;
            As[nb][c0 * 4 + 6][r] = xv1.z; As[nb][c0 * 4 + 7][r] = xv1.w;
            Ws[nb][c0 * 4 + 0][r] = wv0.x; Ws[nb][c0 * 4 + 1][r] = wv0.y;
            Ws[nb][c0 * 4 + 2][r] = wv0.z; Ws[nb][c0 * 4 + 3][r] = wv0.w;
            Ws[nb][c0 * 4 + 4][r] = wv1.x; Ws[nb][c0 * 4 + 5][r] = wv1.y;
            Ws[nb][c0 * 4 + 6][r] = wv1.z; Ws[nb][c0 * 4 + 7][r] = wv1.w;
        }
        __syncthreads();
    }

    float blo_[4], bhi_[4];
#pragma unroll
    for (int j = 0; j < 4; j++) {
        int jlo = j0 + tx * 4 + j;
        int jhi = j0 + 64 + tx * 4 + j;
        blo_[j] = __ldg(&bih[jlo]) + __ldg(&bhh[jlo]);
        bhi_[j] = __ldg(&bih[jhi]) + __ldg(&bhh[jhi]);
    }
#pragma unroll
    for (int i = 0; i < 8; i++) {
        const int m = m0 + ((i < 4) ? (ty * 4 + i) : (64 + ty * 4 + (i - 4)));
        U64F2 p0, p1, p2, p3;
        p0.u = acc[i][0]; p1.u = acc[i][1];
        p2.u = acc[i][2]; p3.u = acc[i][3];
        float4 olo = make_float4(p0.f.x + blo_[0], p0.f.y + blo_[1],
                                 p1.f.x + blo_[2], p1.f.y + blo_[3]);
        float4 ohi = make_float4(p2.f.x + bhi_[0], p2.f.y + bhi_[1],
                                 p3.f.x + bhi_[2], p3.f.y + bhi_[3]);
        *(float4*)&A0[(size_t)m * HD + j0 + tx * 4]      = olo;
        *(float4*)&A0[(size_t)m * HD + j0 + 64 + tx * 4] = ohi;
    }
}

// ---------------- clustered recurrent scan (v6: CSZ=8, L1-resident W) -----
// h(t)[n][j] = tanh(Apre[t][n][j] + sum_k W[j][k] * h(t-1)[n][k])
// 16 clusters x 8 CTAs = 128 CTAs (chip nearly full). Cluster owns 4 batch
// rows; CTA rank owns 64 output cols -> 128KB W slice, L1-RESIDENT after
// step 0 (fits 228KB L1 minus 16KB smem). Full h replicated per CTA; each
// keeper thread publishes its output to all 8 CTAs' hs via DSMEM, then
// cluster barrier (release/acquire).
// Thread map (R14-validated, cb 4->2): w = tid>>5, lane = c2*16 + q.
//   colw = w*2 + c2 (0..31); cb 0..1: local col = cb*32 + colw.
//   Lane k-slice: float4 granules k4 = q + 16*ki, ki 0..7 (32 k's/lane).
//   shfl-xor(8,4,2,1) reduces the 16 q-lanes; keeper q<8 keeps output
//   (row = q>>1, cb = q&1) -> bijection over the CTA's 4x64 outputs.
__global__ __launch_bounds__(RT) __cluster_dims__(CSZ, 1, 1)
void rnn_pass_kernel(const float* __restrict__ W,      // (512,512) row-major
                     const float* __restrict__ Apre,   // (LC*NB, HD)
                     float* __restrict__ Hout,         // (LC*NB, HD)
                     const float* __restrict__ hinit,  // (NB, HD)
                     float* __restrict__ hn)           // (NB, HD)
{
    __shared__ __align__(16) float hs[2][RPC][HD];   // ping-pong full h (16KB)

    const int tid  = threadIdx.x;
    const unsigned int rank = ctarank();             // 0..7
    const int n0   = (blockIdx.x >> 3) * RPC;        // cluster's batch base
    const int slice = (int)rank * COLS_PER_CTA;      // my 64-col W slice

    const int w    = tid >> 5;
    const int lane = tid & 31;
    const int c2   = lane >> 4;            // 0..1
    const int q    = lane & 15;            // 0..15
    const int colw = w * 2 + c2;           // 0..31
    const bool keeper = (q < 8);
    const int myrow = (q >> 1) & 3;        // 0..3 (valid for keepers)
    const int mycl  = (q & 1) * 32 + colw; // 0..63 (col within slice)
    const int gcol  = slice + mycl;        // global output column

    const ulonglong2* Wu = (const ulonglong2*)W;     // 16B granules

    // init h(-1) into buffer 0: 4 rows x 512 cols, coalesced
#pragma unroll
    for (int r = 0; r < RPC; r++) {
        int idx = tid + r * RT;            // 0..2047
        int row = idx >> 9, col = idx & 511;
        hs[0][row][col] = __ldg(&hinit[(n0 + row) * HD + col]);
    }

    // preload Apre for t=0 (keepers only need it; index clamped for others)
    float ac = __ldg(&Apre[(size_t)(n0 + myrow) * HD + gcol]);
    __syncthreads();

    int b = 0;
    for (int t = 0; t < LC; t++) {
        // prefetch next step's Apre (independent of everything below)
        const int tn = (t + 1 < LC) ? (t + 1) : t;
        float ap = __ldg(&Apre[((size_t)tn * NB + n0 + myrow) * HD + gcol]);

        // acc[row][cb]: packed (even,odd) k partials
        unsigned long long acc[RPC][2];
#pragma unroll
        for (int r = 0; r < RPC; r++) { acc[r][0] = 0ULL; acc[r][1] = 0ULL; }

        const ulonglong2* h0u = (const ulonglong2*)&hs[b][0][0];
        const ulonglong2* h1u = (const ulonglong2*)&hs[b][1][0];
        const ulonglong2* h2u = (const ulonglong2*)&hs[b][2][0];
        const ulonglong2* h3u = (const ulonglong2*)&hs[b][3][0];
#pragma unroll
        for (int ki = 0; ki < 8; ki++) {
            const int k4 = q + 16 * ki;              // float4 index 0..127
            ulonglong2 h0 = h0u[k4];                 // LDS.128, conflict-free
            ulonglong2 h1 = h1u[k4];
            ulonglong2 h2 = h2u[k4];
            ulonglong2 h3 = h3u[k4];
#pragma unroll
            for (int cb = 0; cb < 2; cb++) {
                ulonglong2 wv = __ldg(&Wu[(slice + cb * 32 + colw) * 128 + k4]);
                ffma2(acc[0][cb], wv.x, h0.x); ffma2(acc[0][cb], wv.y, h0.y);
                ffma2(acc[1][cb], wv.x, h1.x); ffma2(acc[1][cb], wv.y, h1.y);
                ffma2(acc[2][cb], wv.x, h2.x); ffma2(acc[2][cb], wv.y, h2.y);
                ffma2(acc[3][cb], wv.x, h3.x); ffma2(acc[3][cb], wv.y, h3.y);
            }
        }

        // merge pairs + reduce across the 16 q-lanes (xor 8,4,2,1)
        float v = 0.f;
#pragma unroll
        for (int r = 0; r < RPC; r++) {
#pragma unroll
            for (int cb = 0; cb < 2; cb++) {
                U64F2 m;
                m.u = acc[r][cb];
                float s = m.f.x + m.f.y;
#pragma unroll
                for (int sh = 8; sh > 0; sh >>= 1)
                    s += __shfl_xor_sync(0xffffffffu, s, sh);
                if (q == r * 2 + cb) v = s;          // keeper select (q<8)
            }
        }

        float o = tanhf(v + ac);
        ac = ap;                            // rotate prefetched Apre

        // keepers publish o into hs[b^1][myrow][gcol] of ALL 8 cluster CTAs
        if (keeper) {
            unsigned int base = smem_u32(&hs[b ^ 1][myrow][gcol]);
            hs[b ^ 1][myrow][gcol] = o;     // local copy
#pragma unroll
            for (unsigned int rr = 0; rr < CSZ; rr++)
                if (rr != rank) st_cluster_f32(base, rr, o);
        }
        cluster_sync();                     // release/acquire: h(t) complete

        // flush my 4x64 slice of h(t) to global (coalesced 256B runs)
        if (tid < RPC * COLS_PER_CTA) {
            int row = tid >> 6, cl = tid & 63;
            float hv = hs[b ^ 1][row][slice + cl];
            Hout[((size_t)t * NB + n0 + row) * HD + slice + cl] = hv;
            if (t == LC - 1)
                hn[(n0 + row) * HD + slice + cl] = hv;
        }
        b ^= 1;
    }
}

// ---------------- launch: 4 plain nodes ----------------------------------
extern "C" void kernel_launch(void* const* d_in, const int* in_sizes, int n_in,
                              void* d_out, int out_size) {
    const float* input  = (const float*)d_in[0];
    const float* h_0    = (const float*)d_in[1];
    const float* Wih0   = (const float*)d_in[2];
    const float* Whh0   = (const float*)d_in[3];
    const float* bih0   = (const float*)d_in[4];
    const float* bhh0   = (const float*)d_in[5];
    const float* Wih1   = (const float*)d_in[6];
    const float* Whh1   = (const float*)d_in[7];
    const float* bih1   = (const float*)d_in[8];
    const float* bhh1   = (const float*)d_in[9];
    float* out = (float*)d_out;

    float* hn0 = out + (size_t)LC * NB * HD;            // h_n layer 0
    float* hn1 = hn0 + NB * HD;                          // h_n layer 1

    dim3 ggrid(HD / 128, (LC * NB) / 128);               // (4, 256)

    // 1) A0 = x @ Wih0^T + bih0 + bhh0   (parallel)
    gemm_xW_kernel<<<ggrid, 256>>>(input, Wih0, bih0, bhh0, g_A0);

    // 2) layer-0 scan: h0(t) = tanh(A0[t] + Whh0 h0(t-1)); stores all h0(t)
    rnn_pass_kernel<<<RG, RT>>>(Whh0, g_A0, g_H0, h_0, hn0);

    // 3) X1 = H0 @ Wih1^T + bih1 + bhh1  (parallel)
    gemm_xW_kernel<<<ggrid, 256>>>(g_H0, Wih1, bih1, bhh1, g_X1);

    // 4) layer-1 scan: h1(t) = tanh(X1[t] + Whh1 h1(t-1)); writes `out` rows
    rnn_pass_kernel<<<RG, RT>>>(Whh1, g_X1, out, h_0 + NB * HD, hn1);
}